// round 3
// baseline (speedup 1.0000x reference)
#include <cuda_runtime.h>

#define NEG_BIG 1e30f

// row pitch: 260 floats = 1040 B. 1040 mod 128 = 16 -> successive rows land on
// distinct 16B bank slots => conflict-free LDS.128.
#define PITCHF 260
#define PITCH16 65      // pitch in 16-byte units

// Cross-block scratch: per-block partials (8 batches x 16 blocks) + counters.
__device__ float    g_pM[128];
__device__ float    g_pSe[128];
__device__ float    g_pSec[128];
__device__ unsigned g_cnt[8];   // zero-init; reset to 0 by last block each call

// packed fp32x2 FMA (Blackwell)
__device__ __forceinline__ void ffma2(unsigned long long& d,
                                      unsigned long long a,
                                      unsigned long long b) {
    asm("fma.rn.f32x2 %0, %1, %2, %0;" : "+l"(d) : "l"(a), "l"(b));
}

union U64f2 { unsigned long long u; float2 f; };

__device__ __forceinline__ float wred_max(float v) {
#pragma unroll
    for (int o = 16; o; o >>= 1) v = fmaxf(v, __shfl_xor_sync(0xffffffffu, v, o));
    return v;
}
__device__ __forceinline__ float wred_sum(float v) {
#pragma unroll
    for (int o = 16; o; o >>= 1) v += __shfl_xor_sync(0xffffffffu, v, o);
    return v;
}

// smem layout (floats)
#define OFF_Q    0                       // 64 * 260
#define OFF_CW   (64 * PITCHF)           // 32 * 260
#define OFF_SQC  (OFF_CW + 32 * PITCHF)  // 64
#define OFF_Q1   (OFF_SQC + 64)          // 64
#define OFF_SC   (OFF_Q1 + 64)           // 32
#define OFF_C1   (OFF_SC + 32)           // 32
#define OFF_RM   (OFF_C1 + 32)           // 32*4
#define OFF_RS   (OFF_RM + 128)          // 32*4
#define OFF_RN   (OFF_RS + 128)          // 32*4
#define OFF_MS   (OFF_RN + 128)          // 32  per-row final max
#define OFF_US   (OFF_MS + 32)           // 32  per-row U
#define OFF_H    (OFF_US + 32)           // 1
#define SMEM_FLOATS (OFF_H + 4)
#define SMEM_BYTES  (SMEM_FLOATS * 4)

// Single fused kernel. Grid (16 i-chunks, 8 batches), 256 threads.
// Block tile 32i x 64j x 256d. Warps wi(2) x wj(4); lane li(8) x lj(4);
// lane owns rows {li, li+8} (within warp half) and cols {lj, lj+4, lj+8, lj+12}.
__global__ __launch_bounds__(256) void attn_fused(
    const float* __restrict__ context,   // (8, 512, 256)
    const float* __restrict__ question,  // (8, 64, 256)
    const int*   __restrict__ mask,      // (8, 64)
    const float* __restrict__ att_w,     // (768,)
    const float* __restrict__ att_b,     // (1,)
    const float* __restrict__ w_in,      // (256,)
    const float* __restrict__ w_mem,     // (256,)
    float* __restrict__ out)             // (8, 512, 4)
{
    extern __shared__ float sm[];
    float* qs   = sm + OFF_Q;
    float* cws  = sm + OFF_CW;
    float* sqc  = sm + OFF_SQC;
    float* q1sh = sm + OFF_Q1;
    float* scsh = sm + OFF_SC;
    float* c1sh = sm + OFF_C1;
    float* redM = sm + OFF_RM;
    float* redS = sm + OFF_RS;
    float* redN = sm + OFF_RN;
    float* Msh  = sm + OFF_MS;
    float* Ush  = sm + OFF_US;
    float* Hsh  = sm + OFF_H;

    const int b      = blockIdx.y;
    const int blockI = blockIdx.x * 32;
    const int tid    = threadIdx.x;

    const float* qbase = question + (size_t)(b * 64) * 256;
    const float* cbase = context  + (size_t)(b * 512 + blockI) * 256;

    // ---- stage Q tile (64 x 256) + per-j scalars sq, q1 ----
    {
        const int jq = tid >> 2;        // 0..63
        const int l4 = tid & 3;
        const float4* qrow = (const float4*)(qbase + (size_t)jq * 256);
        float4* qsrow = (float4*)(qs + jq * PITCHF);
        const float4* wq4 = (const float4*)(att_w + 256);
        const float4* wm4 = (const float4*)(w_mem);
        float sq = 0.f, q1 = 0.f;
#pragma unroll
        for (int k = 0; k < 16; k++) {
            int c4 = l4 + (k << 2);
            float4 v = __ldg(&qrow[c4]);
            qsrow[c4] = v;
            float4 a = __ldg(&wq4[c4]);
            float4 m = __ldg(&wm4[c4]);
            sq += v.x * a.x + v.y * a.y + v.z * a.z + v.w * a.w;
            q1 += v.x * m.x + v.y * m.y + v.z * m.z + v.w * m.w;
        }
        sq += __shfl_xor_sync(0xffffffffu, sq, 1);
        sq += __shfl_xor_sync(0xffffffffu, sq, 2);
        q1 += __shfl_xor_sync(0xffffffffu, q1, 1);
        q1 += __shfl_xor_sync(0xffffffffu, q1, 2);
        if (l4 == 0) {
            float mk = (float)__ldg(&mask[b * 64 + jq]);
            sqc[jq]  = sq + __ldg(&att_b[0]) - NEG_BIG * (1.0f - mk);
            q1sh[jq] = q1;
        }
    }

    // ---- stage CW tile (32 x 256) + per-i scalars sc, c1 ----
    {
        const int ic = tid >> 3;        // 0..31
        const int l8 = tid & 7;
        const float4* crow = (const float4*)(cbase + (size_t)ic * 256);
        float4* cwrow = (float4*)(cws + ic * PITCHF);
        const float4* wp4 = (const float4*)(att_w + 512);
        const float4* wc4 = (const float4*)(att_w);
        const float4* wi4 = (const float4*)(w_in);
        float sc = 0.f, c1 = 0.f;
#pragma unroll
        for (int k = 0; k < 8; k++) {
            int c4 = l8 + (k << 3);
            float4 v = __ldg(&crow[c4]);
            float4 p = __ldg(&wp4[c4]);
            cwrow[c4] = make_float4(v.x * p.x, v.y * p.y, v.z * p.z, v.w * p.w);
            float4 a = __ldg(&wc4[c4]);
            float4 m = __ldg(&wi4[c4]);
            sc += v.x * a.x + v.y * a.y + v.z * a.z + v.w * a.w;
            c1 += v.x * m.x + v.y * m.y + v.z * m.z + v.w * m.w;
        }
        sc += __shfl_xor_sync(0xffffffffu, sc, 1);
        sc += __shfl_xor_sync(0xffffffffu, sc, 2);
        sc += __shfl_xor_sync(0xffffffffu, sc, 4);
        c1 += __shfl_xor_sync(0xffffffffu, c1, 1);
        c1 += __shfl_xor_sync(0xffffffffu, c1, 2);
        c1 += __shfl_xor_sync(0xffffffffu, c1, 4);
        if (l8 == 0) { scsh[ic] = sc; c1sh[ic] = c1; }
    }

    __syncthreads();

    // ---- mainloop: S = CW * Q^T, packed f32x2 along d ----
    const int w  = tid >> 5;
    const int l  = tid & 31;
    const int wi = w >> 2;     // 0..1
    const int wj = w & 3;      // 0..3
    const int li = l >> 2;     // 0..7
    const int lj = l & 3;      // 0..3

    const ulonglong2* cr0 = (const ulonglong2*)cws + (wi * 16 + li)     * PITCH16;
    const ulonglong2* cr1 = (const ulonglong2*)cws + (wi * 16 + li + 8) * PITCH16;
    const ulonglong2* q0  = (const ulonglong2*)qs  + (wj * 16 + lj)      * PITCH16;
    const ulonglong2* q1r = (const ulonglong2*)qs  + (wj * 16 + lj + 4)  * PITCH16;
    const ulonglong2* q2r = (const ulonglong2*)qs  + (wj * 16 + lj + 8)  * PITCH16;
    const ulonglong2* q3r = (const ulonglong2*)qs  + (wj * 16 + lj + 12) * PITCH16;

    unsigned long long acc[2][4];
#pragma unroll
    for (int r = 0; r < 2; r++)
#pragma unroll
        for (int j = 0; j < 4; j++) acc[r][j] = 0ull;

#pragma unroll 4
    for (int d = 0; d < 64; d++) {
        ulonglong2 a0 = cr0[d];
        ulonglong2 a1 = cr1[d];
        ulonglong2 b0 = q0[d];
        ulonglong2 b1 = q1r[d];
        ulonglong2 b2 = q2r[d];
        ulonglong2 b3 = q3r[d];
        ffma2(acc[0][0], a0.x, b0.x); ffma2(acc[0][0], a0.y, b0.y);
        ffma2(acc[0][1], a0.x, b1.x); ffma2(acc[0][1], a0.y, b1.y);
        ffma2(acc[0][2], a0.x, b2.x); ffma2(acc[0][2], a0.y, b2.y);
        ffma2(acc[0][3], a0.x, b3.x); ffma2(acc[0][3], a0.y, b3.y);
        ffma2(acc[1][0], a1.x, b0.x); ffma2(acc[1][0], a1.y, b0.y);
        ffma2(acc[1][1], a1.x, b1.x); ffma2(acc[1][1], a1.y, b1.y);
        ffma2(acc[1][2], a1.x, b2.x); ffma2(acc[1][2], a1.y, b2.y);
        ffma2(acc[1][3], a1.x, b3.x); ffma2(acc[1][3], a1.y, b3.y);
    }

    // ---- epilogue: softmax over j (64), U per row ----
    const int il0 = wi * 16 + li;
    const int il1 = il0 + 8;
    const float sc0 = scsh[il0];
    const float sc1 = scsh[il1];

    float s0[4], s1[4], qv[4];
#pragma unroll
    for (int jj = 0; jj < 4; jj++) {
        int j = wj * 16 + lj + 4 * jj;
        float sq = sqc[j];
        qv[jj] = q1sh[j];
        U64f2 u0; u0.u = acc[0][jj];
        U64f2 u1; u1.u = acc[1][jj];
        s0[jj] = u0.f.x + u0.f.y + sc0 + sq;
        s1[jj] = u1.f.x + u1.f.y + sc1 + sq;
    }

    float m0 = fmaxf(fmaxf(s0[0], s0[1]), fmaxf(s0[2], s0[3]));
    float m1 = fmaxf(fmaxf(s1[0], s1[1]), fmaxf(s1[2], s1[3]));
    m0 = fmaxf(m0, __shfl_xor_sync(0xffffffffu, m0, 1));
    m0 = fmaxf(m0, __shfl_xor_sync(0xffffffffu, m0, 2));
    m1 = fmaxf(m1, __shfl_xor_sync(0xffffffffu, m1, 1));
    m1 = fmaxf(m1, __shfl_xor_sync(0xffffffffu, m1, 2));
    if (lj == 0) {
        redM[il0 * 4 + wj] = m0;
        redM[il1 * 4 + wj] = m1;
    }
    __syncthreads();

    float4 M4a = *(const float4*)&redM[il0 * 4];
    float4 M4b = *(const float4*)&redM[il1 * 4];
    const float M0 = fmaxf(fmaxf(M4a.x, M4a.y), fmaxf(M4a.z, M4a.w));
    const float M1 = fmaxf(fmaxf(M4b.x, M4b.y), fmaxf(M4b.z, M4b.w));

    float se0 = 0.f, se1 = 0.f, sn0 = 0.f, sn1 = 0.f;
#pragma unroll
    for (int jj = 0; jj < 4; jj++) {
        float e0 = __expf(s0[jj] - M0);
        float e1 = __expf(s1[jj] - M1);
        se0 += e0; sn0 += e0 * qv[jj];
        se1 += e1; sn1 += e1 * qv[jj];
    }
    se0 += __shfl_xor_sync(0xffffffffu, se0, 1);
    se0 += __shfl_xor_sync(0xffffffffu, se0, 2);
    sn0 += __shfl_xor_sync(0xffffffffu, sn0, 1);
    sn0 += __shfl_xor_sync(0xffffffffu, sn0, 2);
    se1 += __shfl_xor_sync(0xffffffffu, se1, 1);
    se1 += __shfl_xor_sync(0xffffffffu, se1, 2);
    sn1 += __shfl_xor_sync(0xffffffffu, sn1, 1);
    sn1 += __shfl_xor_sync(0xffffffffu, sn1, 2);
    if (lj == 0) {
        redS[il0 * 4 + wj] = se0;
        redS[il1 * 4 + wj] = se1;
        redN[il0 * 4 + wj] = sn0;
        redN[il1 * 4 + wj] = sn1;
    }
    __syncthreads();

    if (wj == 0 && lj == 0) {
        float4 S0 = *(const float4*)&redS[il0 * 4];
        float4 S1 = *(const float4*)&redS[il1 * 4];
        float4 N0 = *(const float4*)&redN[il0 * 4];
        float4 N1 = *(const float4*)&redN[il1 * 4];
        Msh[il0] = M0;
        Msh[il1] = M1;
        Ush[il0] = (N0.x + N0.y + N0.z + N0.w) / (S0.x + S0.y + S0.z + S0.w);
        Ush[il1] = (N1.x + N1.y + N1.z + N1.w) / (S1.x + S1.y + S1.z + S1.w);
    }
    __syncthreads();

    // ---- per-block partial for the batch softmax over i ----
    if (tid < 32) {
        float m  = Msh[tid];
        float c1 = c1sh[tid];
        float Mb  = wred_max(m);
        float e   = __expf(m - Mb);
        float se  = wred_sum(e);
        float sec = wred_sum(e * c1);
        if (tid == 0) {
            int pidx = b * 16 + blockIdx.x;
            g_pM[pidx]   = Mb;
            g_pSe[pidx]  = se;
            g_pSec[pidx] = sec;
            __threadfence();
            atomicAdd(&g_cnt[b], 1u);
            // spin until all 16 blocks of this batch published their partials
            while (*((volatile unsigned*)&g_cnt[b]) < 16u) { __nanosleep(32); }
            __threadfence();
        }
    }
    __syncthreads();

    // ---- combine 16 partials (fixed order per lane -> deterministic) ----
    if (tid < 32) {
        float mb = -3.4e38f, se = 0.f, sec = 0.f;
        if (tid < 16) {
            int pidx = b * 16 + tid;
            mb  = g_pM[pidx];
            se  = g_pSe[pidx];
            sec = g_pSec[pidx];
        }
        float M = wred_max(mb);
        float s = __expf(mb - M);       // lanes >=16 underflow to 0
        float seg  = wred_sum(se * s);
        float secg = wred_sum(sec * s);
        if (tid == 0) Hsh[0] = secg / seg;
    }
    __syncthreads();

    // ---- write output rows ----
    if (tid < 32) {
        float c1 = c1sh[tid];
        float U  = Ush[tid];
        float H  = Hsh[0];
        int idx = b * 512 + blockI + tid;
        ((float4*)out)[idx] = make_float4(c1, U, c1 * U, U * H);
    }

    // ---- counter reset for next graph replay: last block of 2nd round ----
    if (tid == 0) {
        unsigned v = atomicAdd(&g_cnt[b], 1u);
        if (v == 31u) *((volatile unsigned*)&g_cnt[b]) = 0u;
    }
}

extern "C" void kernel_launch(void* const* d_in, const int* in_sizes, int n_in,
                              void* d_out, int out_size)
{
    const float* context  = (const float*)d_in[0];
    const float* question = (const float*)d_in[1];
    const int*   mask     = (const int*)d_in[2];
    const float* att_w    = (const float*)d_in[3];
    const float* att_b    = (const float*)d_in[4];
    const float* w_in     = (const float*)d_in[5];
    const float* w_mem    = (const float*)d_in[6];

    cudaFuncSetAttribute(attn_fused,
                         cudaFuncAttributeMaxDynamicSharedMemorySize, SMEM_BYTES);

    dim3 grid(16, 8);
    attn_fused<<<grid, 256, SMEM_BYTES>>>(context, question, mask,
                                          att_w, att_b, w_in, w_mem,
                                          (float*)d_out);
}